// round 1
// baseline (speedup 1.0000x reference)
#include <cuda_runtime.h>

// Problem constants (from reference): B=16, MAX_LEN=1024, DV=256, H=8, DH=32
#define NB 16
#define DVC 256
#define MAXN 12160   // >= N=12137, padded

// Device scratch (allocation-free requirement)
__device__ float g_qp[MAXN * DVC];
__device__ float g_kp[MAXN * DVC];
__device__ float g_vp[MAXN * DVC];
__device__ float g_att[MAXN * DVC];
__device__ int   g_starts[NB + 1];

// ---------------------------------------------------------------------------
// Kernel 0: segment starts from sorted batch ids
// ---------------------------------------------------------------------------
__global__ void starts_kernel(const int* __restrict__ batch, int N) {
    int i = blockIdx.x * blockDim.x + threadIdx.x;
    if (i == 0) { g_starts[0] = 0; g_starts[NB] = N; }
    if (i > 0 && i < N && batch[i] != batch[i - 1]) g_starts[batch[i]] = i;
}

// ---------------------------------------------------------------------------
// Tiled fp32 SGEMM: C[M,256] = A[M,256] @ W[256,256] + bias
// MODE 0: plain.  MODE 1: C = A + relu(acc + bias)   (final MLP epilogue)
// BM=BN=64, BK=16, 256 threads, 4x4 micro-tile
// ---------------------------------------------------------------------------
template <int MODE>
__global__ void sgemm_kernel(const float* __restrict__ A,
                             const float* __restrict__ W,
                             const float* __restrict__ bias,
                             float* __restrict__ C, int M) {
    __shared__ float As[16][64];   // [k][m]
    __shared__ float Ws[16][64];   // [k][n]

    const int bm = blockIdx.x * 64;
    const int bn = blockIdx.y * 64;
    const int t  = threadIdx.x;
    const int ty = t >> 4;         // 0..15
    const int tx = t & 15;         // 0..15

    const int arow = t >> 2;            // 0..63
    const int acol = (t & 3) * 4;       // 0,4,8,12

    float acc[4][4];
#pragma unroll
    for (int i = 0; i < 4; i++)
#pragma unroll
        for (int j = 0; j < 4; j++) acc[i][j] = 0.f;

    for (int k0 = 0; k0 < 256; k0 += 16) {
        // load A tile (64 x 16), transposed into As[k][m]
        float4 av = make_float4(0.f, 0.f, 0.f, 0.f);
        int gr = bm + arow;
        if (gr < M) av = *(const float4*)&A[gr * 256 + k0 + acol];
        As[acol + 0][arow] = av.x;
        As[acol + 1][arow] = av.y;
        As[acol + 2][arow] = av.z;
        As[acol + 3][arow] = av.w;
        // load W tile (16 x 64)
        float4 wv = *(const float4*)&W[(k0 + ty) * 256 + bn + tx * 4];
        *(float4*)&Ws[ty][tx * 4] = wv;
        __syncthreads();

#pragma unroll
        for (int kk = 0; kk < 16; kk++) {
            float4 a = *(const float4*)&As[kk][ty * 4];
            float4 b = *(const float4*)&Ws[kk][tx * 4];
            acc[0][0] += a.x * b.x; acc[0][1] += a.x * b.y; acc[0][2] += a.x * b.z; acc[0][3] += a.x * b.w;
            acc[1][0] += a.y * b.x; acc[1][1] += a.y * b.y; acc[1][2] += a.y * b.z; acc[1][3] += a.y * b.w;
            acc[2][0] += a.z * b.x; acc[2][1] += a.z * b.y; acc[2][2] += a.z * b.z; acc[2][3] += a.z * b.w;
            acc[3][0] += a.w * b.x; acc[3][1] += a.w * b.y; acc[3][2] += a.w * b.z; acc[3][3] += a.w * b.w;
        }
        __syncthreads();
    }

#pragma unroll
    for (int i = 0; i < 4; i++) {
        int row = bm + ty * 4 + i;
        if (row >= M) continue;
#pragma unroll
        for (int j = 0; j < 4; j++) {
            int col = bn + tx * 4 + j;
            float v = acc[i][j] + bias[col];
            if (MODE == 1) {
                v = A[row * 256 + col] + fmaxf(v, 0.f);
            }
            C[row * 256 + col] = v;
        }
    }
}

// ---------------------------------------------------------------------------
// Attention: block = (q-tile of 32, batch, head). 8 warps x 4 queries each.
// Online softmax, lane-owns-key scoring, residual +qp fused.
// ---------------------------------------------------------------------------
#define TQ 32
__global__ void attn_kernel(float* __restrict__ att) {
    const int b = blockIdx.y;
    const int h = blockIdx.z;
    const int s0 = g_starts[b];
    const int L  = g_starts[b + 1] - s0;
    const int q0 = blockIdx.x * TQ;
    if (q0 >= L) return;

    __shared__ float Qs[TQ][32];
    __shared__ float Ks[32][33];
    __shared__ float Vs[32][33];

    const int t = threadIdx.x;
    const int w = t >> 5;
    const int lane = t & 31;

    // load Q tile (projected q for head h)
    for (int r = w; r < TQ; r += 8) {
        int q = q0 + r;
        Qs[r][lane] = (q < L) ? g_qp[(s0 + q) * 256 + h * 32 + lane] : 0.f;
    }

    float m[4], l[4], o[4], s[4];
#pragma unroll
    for (int i = 0; i < 4; i++) { m[i] = -1e30f; l[i] = 0.f; o[i] = 0.f; }

    const float scale = 0.17677669529663687f;  // 1/sqrt(32)

    for (int ks = 0; ks < L; ks += 32) {
        __syncthreads();  // also covers initial Qs load
        // load K,V chunk (32 keys x 32 dims), coalesced
        for (int j = w; j < 32; j += 8) {
            int kg = ks + j;
            float kv = 0.f, vv = 0.f;
            if (kg < L) {
                kv = g_kp[(s0 + kg) * 256 + h * 32 + lane];
                vv = g_vp[(s0 + kg) * 256 + h * 32 + lane];
            }
            Ks[j][lane] = kv;
            Vs[j][lane] = vv;
        }
        __syncthreads();

        const bool kvalid = (ks + lane) < L;
#pragma unroll
        for (int i = 0; i < 4; i++) s[i] = 0.f;
#pragma unroll
        for (int d = 0; d < 32; d++) {
            float kd = Ks[lane][d];
#pragma unroll
            for (int i = 0; i < 4; i++)
                s[i] += Qs[w * 4 + i][d] * kd;
        }
#pragma unroll
        for (int i = 0; i < 4; i++) {
            float si = kvalid ? s[i] * scale : -1e30f;
            float mx = si;
#pragma unroll
            for (int off = 16; off; off >>= 1)
                mx = fmaxf(mx, __shfl_xor_sync(0xffffffffu, mx, off));
            float mn = fmaxf(m[i], mx);
            float p = __expf(si - mn);
            float corr = __expf(m[i] - mn);
            m[i] = mn;
            float ps = p;
#pragma unroll
            for (int off = 16; off; off >>= 1)
                ps += __shfl_xor_sync(0xffffffffu, ps, off);
            l[i] = l[i] * corr + ps;
            o[i] *= corr;
            s[i] = p;  // reuse as softmax numerator
        }
        // o[i] (d = lane) += sum_j p_j * V[j][lane]
#pragma unroll
        for (int j = 0; j < 32; j++) {
            float v = Vs[j][lane];
#pragma unroll
            for (int i = 0; i < 4; i++) {
                float pj = __shfl_sync(0xffffffffu, s[i], j);
                o[i] += pj * v;
            }
        }
    }

#pragma unroll
    for (int i = 0; i < 4; i++) {
        int q = q0 + w * 4 + i;
        if (q < L) {
            float val = o[i] / l[i] + Qs[w * 4 + i][lane];  // residual with projected q
            att[(s0 + q) * 256 + h * 32 + lane] = val;
        }
    }
}

// ---------------------------------------------------------------------------
// Launch
// ---------------------------------------------------------------------------
extern "C" void kernel_launch(void* const* d_in, const int* in_sizes, int n_in,
                              void* d_out, int out_size) {
    const float* q   = (const float*)d_in[0];
    const float* k   = (const float*)d_in[1];
    const int* batch_q = (const int*)d_in[2];
    // d_in[3] = batch_k (identical segments)
    const float* Wq = (const float*)d_in[4];
    const float* bq = (const float*)d_in[5];
    const float* Wk = (const float*)d_in[6];
    const float* bk = (const float*)d_in[7];
    const float* Wv = (const float*)d_in[8];
    const float* bv = (const float*)d_in[9];
    const float* Wo = (const float*)d_in[10];
    const float* bo = (const float*)d_in[11];
    float* out = (float*)d_out;

    const int N = in_sizes[0] / 256;

    float* qp;  cudaGetSymbolAddress((void**)&qp,  g_qp);
    float* kp;  cudaGetSymbolAddress((void**)&kp,  g_kp);
    float* vp;  cudaGetSymbolAddress((void**)&vp,  g_vp);
    float* att; cudaGetSymbolAddress((void**)&att, g_att);

    starts_kernel<<<(N + 255) / 256, 256>>>(batch_q, N);

    dim3 ggrid((N + 63) / 64, 4);
    sgemm_kernel<0><<<ggrid, 256>>>(q, Wq, bq, qp, N);
    sgemm_kernel<0><<<ggrid, 256>>>(k, Wk, bk, kp, N);
    sgemm_kernel<0><<<ggrid, 256>>>(k, Wv, bv, vp, N);

    dim3 agrid(1024 / TQ, NB, 8);
    attn_kernel<<<agrid, 256>>>(att);

    sgemm_kernel<1><<<ggrid, 256>>>(att, Wo, bo, out, N);
}

// round 3
// speedup vs baseline: 2.5099x; 2.5099x over previous
#include <cuda_runtime.h>
#include <cstdint>

// Problem constants: B=16, MAX_LEN=1024, DV=256, H=8, DH=32
#define NB 16
#define DVC 256
#define MAXN 12160

// Device scratch (allocation-free requirement)
__device__ float g_qp[MAXN * DVC];
__device__ float g_kp[MAXN * DVC];
__device__ float g_vp[MAXN * DVC];
__device__ float g_att[MAXN * DVC];
__device__ int   g_starts[NB + 1];

// ---------------------------------------------------------------------------
// Kernel 0: segment starts from sorted batch ids
// ---------------------------------------------------------------------------
__global__ void starts_kernel(const int* __restrict__ batch, int N) {
    int i = blockIdx.x * blockDim.x + threadIdx.x;
    if (i == 0) { g_starts[0] = 0; g_starts[NB] = N; }
    if (i > 0 && i < N && batch[i] != batch[i - 1]) g_starts[batch[i]] = i;
}

// ---------------------------------------------------------------------------
// Tiled fp32 SGEMM
// ---------------------------------------------------------------------------
template <int MODE>
__global__ void sgemm_kernel(const float* __restrict__ A,
                             const float* __restrict__ W,
                             const float* __restrict__ bias,
                             float* __restrict__ C, int M) {
    __shared__ float As[16][64];
    __shared__ float Ws[16][64];

    const int bm = blockIdx.x * 64;
    const int bn = blockIdx.y * 64;
    const int t  = threadIdx.x;
    const int ty = t >> 4;
    const int tx = t & 15;

    const int arow = t >> 2;
    const int acol = (t & 3) * 4;

    float acc[4][4];
#pragma unroll
    for (int i = 0; i < 4; i++)
#pragma unroll
        for (int j = 0; j < 4; j++) acc[i][j] = 0.f;

    for (int k0 = 0; k0 < 256; k0 += 16) {
        float4 av = make_float4(0.f, 0.f, 0.f, 0.f);
        int gr = bm + arow;
        if (gr < M) av = *(const float4*)&A[gr * 256 + k0 + acol];
        As[acol + 0][arow] = av.x;
        As[acol + 1][arow] = av.y;
        As[acol + 2][arow] = av.z;
        As[acol + 3][arow] = av.w;
        float4 wv = *(const float4*)&W[(k0 + ty) * 256 + bn + tx * 4];
        *(float4*)&Ws[ty][tx * 4] = wv;
        __syncthreads();

#pragma unroll
        for (int kk = 0; kk < 16; kk++) {
            float4 a = *(const float4*)&As[kk][ty * 4];
            float4 b = *(const float4*)&Ws[kk][tx * 4];
            acc[0][0] += a.x * b.x; acc[0][1] += a.x * b.y; acc[0][2] += a.x * b.z; acc[0][3] += a.x * b.w;
            acc[1][0] += a.y * b.x; acc[1][1] += a.y * b.y; acc[1][2] += a.y * b.z; acc[1][3] += a.y * b.w;
            acc[2][0] += a.z * b.x; acc[2][1] += a.z * b.y; acc[2][2] += a.z * b.z; acc[2][3] += a.z * b.w;
            acc[3][0] += a.w * b.x; acc[3][1] += a.w * b.y; acc[3][2] += a.w * b.z; acc[3][3] += a.w * b.w;
        }
        __syncthreads();
    }

#pragma unroll
    for (int i = 0; i < 4; i++) {
        int row = bm + ty * 4 + i;
        if (row >= M) continue;
#pragma unroll
        for (int j = 0; j < 4; j++) {
            int col = bn + tx * 4 + j;
            float v = acc[i][j] + bias[col];
            if (MODE == 1) v = A[row * 256 + col] + fmaxf(v, 0.f);
            C[row * 256 + col] = v;
        }
    }
}

// ---------------------------------------------------------------------------
// tf32 mma helpers
// ---------------------------------------------------------------------------
__device__ __forceinline__ uint32_t f2tf32(float f) {
    uint32_t u;
    asm("cvt.rna.tf32.f32 %0, %1;" : "=r"(u) : "f"(f));
    return u;
}
__device__ __forceinline__ float f2tf32f(float f) {
    return __uint_as_float(f2tf32(f));
}
__device__ __forceinline__ void mma_tf32(float c[4], const uint32_t a[4],
                                         uint32_t b0, uint32_t b1) {
    asm volatile(
        "mma.sync.aligned.m16n8k8.row.col.f32.tf32.tf32.f32 "
        "{%0,%1,%2,%3}, {%4,%5,%6,%7}, {%8,%9}, {%0,%1,%2,%3};"
        : "+f"(c[0]), "+f"(c[1]), "+f"(c[2]), "+f"(c[3])
        : "r"(a[0]), "r"(a[1]), "r"(a[2]), "r"(a[3]), "r"(b0), "r"(b1));
}

// ---------------------------------------------------------------------------
// Attention with tf32 tensor cores.
// Block = (64-query tile, batch, head), 4 warps, each warp owns 16 queries.
// Key chunks of 32. Online softmax on fragments. Residual +qp fused.
// ---------------------------------------------------------------------------
#define ATQ 64
__global__ void attn_kernel(float* __restrict__ att) {
    const int b = blockIdx.y;
    const int h = blockIdx.z;
    const int s0 = g_starts[b];
    const int L  = g_starts[b + 1] - s0;
    const int q0 = blockIdx.x * ATQ;
    if (q0 >= L) return;

    __shared__ float Ks[32][36];      // [key][d], tf32-rounded
    __shared__ float Vs[32][36];      // [key][d], tf32-rounded
    __shared__ float Ps[4][16][36];   // per-warp P tile [qrow][key]

    const int tid  = threadIdx.x;
    const int w    = tid >> 5;
    const int lane = tid & 31;
    const int g    = lane >> 2;   // 0..7  (fragment row group)
    const int m4   = lane & 3;    // 0..3

    const int q0w = q0 + w * 16;  // this warp's first query row (local)
    const float scale = 0.17677669529663687f;  // 1/sqrt(32)

    // Q fragments, register-resident for the whole kernel. Pre-scaled.
    uint32_t qa[4][4];
#pragma unroll
    for (int ks = 0; ks < 4; ks++) {
        int d0 = ks * 8 + m4;
        int r0 = q0w + g, r1 = q0w + g + 8;
        float v00 = (r0 < L) ? g_qp[(s0 + r0) * 256 + h * 32 + d0]     : 0.f;
        float v10 = (r1 < L) ? g_qp[(s0 + r1) * 256 + h * 32 + d0]     : 0.f;
        float v01 = (r0 < L) ? g_qp[(s0 + r0) * 256 + h * 32 + d0 + 4] : 0.f;
        float v11 = (r1 < L) ? g_qp[(s0 + r1) * 256 + h * 32 + d0 + 4] : 0.f;
        qa[ks][0] = f2tf32(v00 * scale);
        qa[ks][1] = f2tf32(v10 * scale);
        qa[ks][2] = f2tf32(v01 * scale);
        qa[ks][3] = f2tf32(v11 * scale);
    }

    float o[4][4];
#pragma unroll
    for (int i = 0; i < 4; i++)
#pragma unroll
        for (int j = 0; j < 4; j++) o[i][j] = 0.f;
    float m0 = -1e30f, m1 = -1e30f, l0 = 0.f, l1 = 0.f;

    for (int kc = 0; kc < L; kc += 32) {
        __syncthreads();
        // cooperative K/V chunk load (tf32-rounded), coalesced
#pragma unroll
        for (int i = 0; i < 8; i++) {
            int j = (tid >> 5) + i * 4;     // key row 0..31
            int col = tid & 31;             // d
            int kg = kc + j;
            float kv = 0.f, vv = 0.f;
            if (kg < L) {
                int base = (s0 + kg) * 256 + h * 32 + col;
                kv = g_kp[base];
                vv = g_vp[base];
            }
            Ks[j][col] = f2tf32f(kv);
            Vs[j][col] = f2tf32f(vv);
        }
        __syncthreads();

        // ---- QK^T: S[16][32] per warp ----
        float sc[4][4];
#pragma unroll
        for (int nt = 0; nt < 4; nt++)
#pragma unroll
            for (int j = 0; j < 4; j++) sc[nt][j] = 0.f;
#pragma unroll
        for (int ks = 0; ks < 4; ks++) {
#pragma unroll
            for (int nt = 0; nt < 4; nt++) {
                uint32_t b0 = __float_as_uint(Ks[nt * 8 + g][ks * 8 + m4]);
                uint32_t b1 = __float_as_uint(Ks[nt * 8 + g][ks * 8 + m4 + 4]);
                mma_tf32(sc[nt], qa[ks], b0, b1);
            }
        }

        // ---- mask + online softmax (fragment layout) ----
        float mx0 = -1e30f, mx1 = -1e30f;
#pragma unroll
        for (int nt = 0; nt < 4; nt++) {
            int kcol0 = kc + nt * 8 + 2 * m4;
            if (kcol0 >= L)     { sc[nt][0] = -1e30f; sc[nt][2] = -1e30f; }
            if (kcol0 + 1 >= L) { sc[nt][1] = -1e30f; sc[nt][3] = -1e30f; }
            mx0 = fmaxf(mx0, fmaxf(sc[nt][0], sc[nt][1]));
            mx1 = fmaxf(mx1, fmaxf(sc[nt][2], sc[nt][3]));
        }
        mx0 = fmaxf(mx0, __shfl_xor_sync(0xffffffffu, mx0, 1));
        mx0 = fmaxf(mx0, __shfl_xor_sync(0xffffffffu, mx0, 2));
        mx1 = fmaxf(mx1, __shfl_xor_sync(0xffffffffu, mx1, 1));
        mx1 = fmaxf(mx1, __shfl_xor_sync(0xffffffffu, mx1, 2));

        float m0n = fmaxf(m0, mx0);
        float m1n = fmaxf(m1, mx1);
        float c0 = __expf(m0 - m0n);
        float c1 = __expf(m1 - m1n);
        m0 = m0n; m1 = m1n;

        float s0r = 0.f, s1r = 0.f;
#pragma unroll
        for (int nt = 0; nt < 4; nt++) {
            float p00 = __expf(sc[nt][0] - m0n);
            float p01 = __expf(sc[nt][1] - m0n);
            float p10 = __expf(sc[nt][2] - m1n);
            float p11 = __expf(sc[nt][3] - m1n);
            s0r += p00 + p01;
            s1r += p10 + p11;
            int col = nt * 8 + 2 * m4;
            Ps[w][g][col]         = f2tf32f(p00);
            Ps[w][g][col + 1]     = f2tf32f(p01);
            Ps[w][g + 8][col]     = f2tf32f(p10);
            Ps[w][g + 8][col + 1] = f2tf32f(p11);
        }
        s0r += __shfl_xor_sync(0xffffffffu, s0r, 1);
        s0r += __shfl_xor_sync(0xffffffffu, s0r, 2);
        s1r += __shfl_xor_sync(0xffffffffu, s1r, 1);
        s1r += __shfl_xor_sync(0xffffffffu, s1r, 2);
        l0 = l0 * c0 + s0r;
        l1 = l1 * c1 + s1r;

        // rescale existing accumulators
#pragma unroll
        for (int nt = 0; nt < 4; nt++) {
            o[nt][0] *= c0; o[nt][1] *= c0;
            o[nt][2] *= c1; o[nt][3] *= c1;
        }

        __syncwarp();

        // ---- PV: O[16][32] += P[16][32] @ V[32][32] ----
#pragma unroll
        for (int ks = 0; ks < 4; ks++) {
            uint32_t pa[4];
            pa[0] = __float_as_uint(Ps[w][g][ks * 8 + m4]);
            pa[1] = __float_as_uint(Ps[w][g + 8][ks * 8 + m4]);
            pa[2] = __float_as_uint(Ps[w][g][ks * 8 + m4 + 4]);
            pa[3] = __float_as_uint(Ps[w][g + 8][ks * 8 + m4 + 4]);
#pragma unroll
            for (int nt = 0; nt < 4; nt++) {
                uint32_t b0 = __float_as_uint(Vs[ks * 8 + m4][nt * 8 + g]);
                uint32_t b1 = __float_as_uint(Vs[ks * 8 + m4 + 4][nt * 8 + g]);
                mma_tf32(o[nt], pa, b0, b1);
            }
        }
    }

    // ---- epilogue: normalize, residual +qp, store ----
    float il0 = 1.f / l0, il1 = 1.f / l1;
    int r0 = q0w + g, r1 = q0w + g + 8;
#pragma unroll
    for (int nt = 0; nt < 4; nt++) {
        int dh = nt * 8 + 2 * m4;
        if (r0 < L) {
            int base = (s0 + r0) * 256 + h * 32 + dh;
            float2 qv = *(const float2*)&g_qp[base];
            float2 ov = make_float2(o[nt][0] * il0 + qv.x, o[nt][1] * il0 + qv.y);
            *(float2*)&att[base] = ov;
        }
        if (r1 < L) {
            int base = (s0 + r1) * 256 + h * 32 + dh;
            float2 qv = *(const float2*)&g_qp[base];
            float2 ov = make_float2(o[nt][2] * il1 + qv.x, o[nt][3] * il1 + qv.y);
            *(float2*)&att[base] = ov;
        }
    }
}

// ---------------------------------------------------------------------------
// Launch
// ---------------------------------------------------------------------------
extern "C" void kernel_launch(void* const* d_in, const int* in_sizes, int n_in,
                              void* d_out, int out_size) {
    const float* q   = (const float*)d_in[0];
    const float* k   = (const float*)d_in[1];
    const int* batch_q = (const int*)d_in[2];
    const float* Wq = (const float*)d_in[4];
    const float* bq = (const float*)d_in[5];
    const float* Wk = (const float*)d_in[6];
    const float* bk = (const float*)d_in[7];
    const float* Wv = (const float*)d_in[8];
    const float* bv = (const float*)d_in[9];
    const float* Wo = (const float*)d_in[10];
    const float* bo = (const float*)d_in[11];
    float* out = (float*)d_out;

    const int N = in_sizes[0] / 256;

    float* qp;  cudaGetSymbolAddress((void**)&qp,  g_qp);
    float* kp;  cudaGetSymbolAddress((void**)&kp,  g_kp);
    float* vp;  cudaGetSymbolAddress((void**)&vp,  g_vp);
    float* att; cudaGetSymbolAddress((void**)&att, g_att);

    starts_kernel<<<(N + 255) / 256, 256>>>(batch_q, N);

    dim3 ggrid((N + 63) / 64, 4);
    sgemm_kernel<0><<<ggrid, 256>>>(q, Wq, bq, qp, N);
    sgemm_kernel<0><<<ggrid, 256>>>(k, Wk, bk, kp, N);
    sgemm_kernel<0><<<ggrid, 256>>>(k, Wv, bv, vp, N);

    dim3 agrid(1024 / ATQ, NB, 8);
    attn_kernel<<<agrid, 128>>>(att);

    sgemm_kernel<1><<<ggrid, 256>>>(att, Wo, bo, out, N);
}

// round 5
// speedup vs baseline: 4.0030x; 1.5949x over previous
#include <cuda_runtime.h>
#include <cstdint>

// Problem constants: B=16, MAX_LEN=1024, DV=256, H=8, DH=32
#define NB 16
#define DVC 256
#define MAXN 12160

// Device scratch (allocation-free requirement)
__device__ float g_qp[MAXN * DVC];
__device__ float g_kp[MAXN * DVC];
__device__ float g_vp[MAXN * DVC];
__device__ float g_att[MAXN * DVC];
__device__ int   g_starts[NB + 1];

// ---------------------------------------------------------------------------
// tf32 mma helpers
// ---------------------------------------------------------------------------
__device__ __forceinline__ uint32_t f2tf32(float f) {
    uint32_t u;
    asm("cvt.rna.tf32.f32 %0, %1;" : "=r"(u) : "f"(f));
    return u;
}
__device__ __forceinline__ float f2tf32f(float f) {
    return __uint_as_float(f2tf32(f));
}
__device__ __forceinline__ void mma_tf32(float c[4], const uint32_t a[4],
                                         uint32_t b0, uint32_t b1) {
    asm volatile(
        "mma.sync.aligned.m16n8k8.row.col.f32.tf32.tf32.f32 "
        "{%0,%1,%2,%3}, {%4,%5,%6,%7}, {%8,%9}, {%0,%1,%2,%3};"
        : "+f"(c[0]), "+f"(c[1]), "+f"(c[2]), "+f"(c[3])
        : "r"(a[0]), "r"(a[1]), "r"(a[2]), "r"(a[3]), "r"(b0), "r"(b1));
}

// ---------------------------------------------------------------------------
// Kernel 0: segment starts from sorted batch ids
// ---------------------------------------------------------------------------
__global__ void starts_kernel(const int* __restrict__ batch, int N) {
    int i = blockIdx.x * blockDim.x + threadIdx.x;
    if (i == 0) { g_starts[0] = 0; g_starts[NB] = N; }
    if (i > 0 && i < N && batch[i] != batch[i - 1]) g_starts[batch[i]] = i;
}

// ---------------------------------------------------------------------------
// tf32 tensor-core GEMM: C[M,256] = A[M,256] @ W[256,256] + bias
// MODE 0: plain.  MODE 1: C = A + relu(acc + bias)
// 128 threads = 4 warps in 2x2; block tile 64x64; BK=32; warp tile 32x32.
// Conflict-free fragment reads: As[64][36] (bank=4g+m4), Ws[32][72] (bank=8m4+g).
// ---------------------------------------------------------------------------
template <int MODE>
__global__ void tgemm_kernel(const float* __restrict__ A,
                             const float* __restrict__ W,
                             const float* __restrict__ bias,
                             float* __restrict__ C, int M) {
    __shared__ float As[64][36];
    __shared__ float Ws[32][72];

    const int bm = blockIdx.x * 64;
    const int bn = blockIdx.y * 64;
    const int tid  = threadIdx.x;
    const int w    = tid >> 5;
    const int lane = tid & 31;
    const int g    = lane >> 2;
    const int m4   = lane & 3;
    const int wm   = (w >> 1) * 32;
    const int wn   = (w & 1) * 32;

    float acc[2][4][4];
#pragma unroll
    for (int mt = 0; mt < 2; mt++)
#pragma unroll
        for (int nt = 0; nt < 4; nt++)
#pragma unroll
            for (int j = 0; j < 4; j++) acc[mt][nt][j] = 0.f;

    for (int k0 = 0; k0 < 256; k0 += 32) {
        // A tile 64x32 (tf32-rounded at store)
#pragma unroll
        for (int i = 0; i < 4; i++) {
            int s = tid + i * 128;
            int r = s >> 3, c = (s & 7) * 4;
            float4 v = make_float4(0.f, 0.f, 0.f, 0.f);
            if (bm + r < M) v = *(const float4*)&A[(bm + r) * 256 + k0 + c];
            As[r][c + 0] = f2tf32f(v.x);
            As[r][c + 1] = f2tf32f(v.y);
            As[r][c + 2] = f2tf32f(v.z);
            As[r][c + 3] = f2tf32f(v.w);
        }
        // W tile 32x64
#pragma unroll
        for (int i = 0; i < 4; i++) {
            int s = tid + i * 128;
            int r = s >> 4, c = (s & 15) * 4;
            float4 v = *(const float4*)&W[(k0 + r) * 256 + bn + c];
            Ws[r][c + 0] = f2tf32f(v.x);
            Ws[r][c + 1] = f2tf32f(v.y);
            Ws[r][c + 2] = f2tf32f(v.z);
            Ws[r][c + 3] = f2tf32f(v.w);
        }
        __syncthreads();

#pragma unroll
        for (int k8 = 0; k8 < 4; k8++) {
            uint32_t a[2][4];
#pragma unroll
            for (int mt = 0; mt < 2; mt++) {
                int mr = wm + mt * 16;
                a[mt][0] = __float_as_uint(As[mr + g    ][k8 * 8 + m4]);
                a[mt][1] = __float_as_uint(As[mr + g + 8][k8 * 8 + m4]);
                a[mt][2] = __float_as_uint(As[mr + g    ][k8 * 8 + m4 + 4]);
                a[mt][3] = __float_as_uint(As[mr + g + 8][k8 * 8 + m4 + 4]);
            }
#pragma unroll
            for (int nt = 0; nt < 4; nt++) {
                uint32_t b0 = __float_as_uint(Ws[k8 * 8 + m4    ][wn + nt * 8 + g]);
                uint32_t b1 = __float_as_uint(Ws[k8 * 8 + m4 + 4][wn + nt * 8 + g]);
                mma_tf32(acc[0][nt], a[0], b0, b1);
                mma_tf32(acc[1][nt], a[1], b0, b1);
            }
        }
        __syncthreads();
    }

    // epilogue
#pragma unroll
    for (int mt = 0; mt < 2; mt++) {
#pragma unroll
        for (int i = 0; i < 2; i++) {
            int row = bm + wm + mt * 16 + g + i * 8;
            if (row >= M) continue;
#pragma unroll
            for (int nt = 0; nt < 4; nt++) {
                int col = bn + wn + nt * 8 + 2 * m4;
                float x = acc[mt][nt][i * 2 + 0] + bias[col];
                float y = acc[mt][nt][i * 2 + 1] + bias[col + 1];
                if (MODE == 1) {
                    float2 av = *(const float2*)&A[row * 256 + col];
                    x = av.x + fmaxf(x, 0.f);
                    y = av.y + fmaxf(y, 0.f);
                }
                *(float2*)&C[row * 256 + col] = make_float2(x, y);
            }
        }
    }
}

// ---------------------------------------------------------------------------
// Attention with tf32 tensor cores.
// Block = (64-query tile, batch, head), 4 warps, each warp owns 16 queries.
// ---------------------------------------------------------------------------
#define ATQ 64
__global__ void attn_kernel(float* __restrict__ att) {
    const int b = blockIdx.y;
    const int h = blockIdx.z;
    const int s0 = g_starts[b];
    const int L  = g_starts[b + 1] - s0;
    const int q0 = blockIdx.x * ATQ;
    if (q0 >= L) return;

    __shared__ float Ks[32][36];
    __shared__ float Vs[32][36];
    __shared__ float Ps[4][16][36];

    const int tid  = threadIdx.x;
    const int w    = tid >> 5;
    const int lane = tid & 31;
    const int g    = lane >> 2;
    const int m4   = lane & 3;

    const int q0w = q0 + w * 16;
    const float scale = 0.17677669529663687f;

    uint32_t qa[4][4];
#pragma unroll
    for (int ks = 0; ks < 4; ks++) {
        int d0 = ks * 8 + m4;
        int r0 = q0w + g, r1 = q0w + g + 8;
        float v00 = (r0 < L) ? g_qp[(s0 + r0) * 256 + h * 32 + d0]     : 0.f;
        float v10 = (r1 < L) ? g_qp[(s0 + r1) * 256 + h * 32 + d0]     : 0.f;
        float v01 = (r0 < L) ? g_qp[(s0 + r0) * 256 + h * 32 + d0 + 4] : 0.f;
        float v11 = (r1 < L) ? g_qp[(s0 + r1) * 256 + h * 32 + d0 + 4] : 0.f;
        qa[ks][0] = f2tf32(v00 * scale);
        qa[ks][1] = f2tf32(v10 * scale);
        qa[ks][2] = f2tf32(v01 * scale);
        qa[ks][3] = f2tf32(v11 * scale);
    }

    float o[4][4];
#pragma unroll
    for (int i = 0; i < 4; i++)
#pragma unroll
        for (int j = 0; j < 4; j++) o[i][j] = 0.f;
    float m0 = -1e30f, m1 = -1e30f, l0 = 0.f, l1 = 0.f;

    for (int kc = 0; kc < L; kc += 32) {
        __syncthreads();
#pragma unroll
        for (int i = 0; i < 8; i++) {
            int j = (tid >> 5) + i * 4;
            int col = tid & 31;
            int kg = kc + j;
            float kv = 0.f, vv = 0.f;
            if (kg < L) {
                int base = (s0 + kg) * 256 + h * 32 + col;
                kv = g_kp[base];
                vv = g_vp[base];
            }
            Ks[j][col] = f2tf32f(kv);
            Vs[j][col] = f2tf32f(vv);
        }
        __syncthreads();

        float sc[4][4];
#pragma unroll
        for (int nt = 0; nt < 4; nt++)
#pragma unroll
            for (int j = 0; j < 4; j++) sc[nt][j] = 0.f;
#pragma unroll
        for (int ks = 0; ks < 4; ks++) {
#pragma unroll
            for (int nt = 0; nt < 4; nt++) {
                uint32_t b0 = __float_as_uint(Ks[nt * 8 + g][ks * 8 + m4]);
                uint32_t b1 = __float_as_uint(Ks[nt * 8 + g][ks * 8 + m4 + 4]);
                mma_tf32(sc[nt], qa[ks], b0, b1);
            }
        }

        float mx0 = -1e30f, mx1 = -1e30f;
#pragma unroll
        for (int nt = 0; nt < 4; nt++) {
            int kcol0 = kc + nt * 8 + 2 * m4;
            if (kcol0 >= L)     { sc[nt][0] = -1e30f; sc[nt][2] = -1e30f; }
            if (kcol0 + 1 >= L) { sc[nt][1] = -1e30f; sc[nt][3] = -1e30f; }
            mx0 = fmaxf(mx0, fmaxf(sc[nt][0], sc[nt][1]));
            mx1 = fmaxf(mx1, fmaxf(sc[nt][2], sc[nt][3]));
        }
        mx0 = fmaxf(mx0, __shfl_xor_sync(0xffffffffu, mx0, 1));
        mx0 = fmaxf(mx0, __shfl_xor_sync(0xffffffffu, mx0, 2));
        mx1 = fmaxf(mx1, __shfl_xor_sync(0xffffffffu, mx1, 1));
        mx1 = fmaxf(mx1, __shfl_xor_sync(0xffffffffu, mx1, 2));

        float m0n = fmaxf(m0, mx0);
        float m1n = fmaxf(m1, mx1);
        float c0 = __expf(m0 - m0n);
        float c1 = __expf(m1 - m1n);
        m0 = m0n; m1 = m1n;

        float s0r = 0.f, s1r = 0.f;
#pragma unroll
        for (int nt = 0; nt < 4; nt++) {
            float p00 = __expf(sc[nt][0] - m0n);
            float p01 = __expf(sc[nt][1] - m0n);
            float p10 = __expf(sc[nt][2] - m1n);
            float p11 = __expf(sc[nt][3] - m1n);
            s0r += p00 + p01;
            s1r += p10 + p11;
            int col = nt * 8 + 2 * m4;
            Ps[w][g][col]         = f2tf32f(p00);
            Ps[w][g][col + 1]     = f2tf32f(p01);
            Ps[w][g + 8][col]     = f2tf32f(p10);
            Ps[w][g + 8][col + 1] = f2tf32f(p11);
        }
        s0r += __shfl_xor_sync(0xffffffffu, s0r, 1);
        s0r += __shfl_xor_sync(0xffffffffu, s0r, 2);
        s1r += __shfl_xor_sync(0xffffffffu, s1r, 1);
        s1r += __shfl_xor_sync(0xffffffffu, s1r, 2);
        l0 = l0 * c0 + s0r;
        l1 = l1 * c1 + s1r;

#pragma unroll
        for (int nt = 0; nt < 4; nt++) {
            o[nt][0] *= c0; o[nt][1] *= c0;
            o[nt][2] *= c1; o[nt][3] *= c1;
        }

        __syncwarp();

#pragma unroll
        for (int ks = 0; ks < 4; ks++) {
            uint32_t pa[4];
            pa[0] = __float_as_uint(Ps[w][g][ks * 8 + m4]);
            pa[1] = __float_as_uint(Ps[w][g + 8][ks * 8 + m4]);
            pa[2] = __float_as_uint(Ps[w][g][ks * 8 + m4 + 4]);
            pa[3] = __float_as_uint(Ps[w][g + 8][ks * 8 + m4 + 4]);
#pragma unroll
            for (int nt = 0; nt < 4; nt++) {
                uint32_t b0 = __float_as_uint(Vs[ks * 8 + m4][nt * 8 + g]);
                uint32_t b1 = __float_as_uint(Vs[ks * 8 + m4 + 4][nt * 8 + g]);
                mma_tf32(o[nt], pa, b0, b1);
            }
        }
    }

    float il0 = 1.f / l0, il1 = 1.f / l1;
    int r0 = q0w + g, r1 = q0w + g + 8;
#pragma unroll
    for (int nt = 0; nt < 4; nt++) {
        int dh = nt * 8 + 2 * m4;
        if (r0 < L) {
            int base = (s0 + r0) * 256 + h * 32 + dh;
            float2 qv = *(const float2*)&g_qp[base];
            float2 ov = make_float2(o[nt][0] * il0 + qv.x, o[nt][1] * il0 + qv.y);
            *(float2*)&att[base] = ov;
        }
        if (r1 < L) {
            int base = (s0 + r1) * 256 + h * 32 + dh;
            float2 qv = *(const float2*)&g_qp[base];
            float2 ov = make_float2(o[nt][2] * il1 + qv.x, o[nt][3] * il1 + qv.y);
            *(float2*)&att[base] = ov;
        }
    }
}

// ---------------------------------------------------------------------------
// Launch
// ---------------------------------------------------------------------------
extern "C" void kernel_launch(void* const* d_in, const int* in_sizes, int n_in,
                              void* d_out, int out_size) {
    const float* q   = (const float*)d_in[0];
    const float* k   = (const float*)d_in[1];
    const int* batch_q = (const int*)d_in[2];
    const float* Wq = (const float*)d_in[4];
    const float* bq = (const float*)d_in[5];
    const float* Wk = (const float*)d_in[6];
    const float* bk = (const float*)d_in[7];
    const float* Wv = (const float*)d_in[8];
    const float* bv = (const float*)d_in[9];
    const float* Wo = (const float*)d_in[10];
    const float* bo = (const float*)d_in[11];
    float* out = (float*)d_out;

    const int N = in_sizes[0] / 256;

    float* qp;  cudaGetSymbolAddress((void**)&qp,  g_qp);
    float* kp;  cudaGetSymbolAddress((void**)&kp,  g_kp);
    float* vp;  cudaGetSymbolAddress((void**)&vp,  g_vp);
    float* att; cudaGetSymbolAddress((void**)&att, g_att);

    starts_kernel<<<(N + 255) / 256, 256>>>(batch_q, N);

    dim3 ggrid((N + 63) / 64, 4);
    tgemm_kernel<0><<<ggrid, 128>>>(q, Wq, bq, qp, N);
    tgemm_kernel<0><<<ggrid, 128>>>(k, Wk, bk, kp, N);
    tgemm_kernel<0><<<ggrid, 128>>>(k, Wv, bv, vp, N);

    dim3 agrid(1024 / ATQ, NB, 8);
    attn_kernel<<<agrid, 128>>>(att);

    tgemm_kernel<1><<<ggrid, 128>>>(att, Wo, bo, out, N);
}

// round 7
// speedup vs baseline: 4.3591x; 1.0889x over previous
#include <cuda_runtime.h>
#include <cstdint>

// Problem constants: B=16, MAX_LEN=1024, DV=256, H=8, DH=32
#define NB 16
#define DVC 256
#define MAXN 12160

// Device scratch (allocation-free requirement)
__device__ float g_qp[MAXN * DVC];
__device__ float g_kp[MAXN * DVC];
__device__ float g_vp[MAXN * DVC];
__device__ float g_att[MAXN * DVC];
__device__ int   g_starts[NB + 1];

// ---------------------------------------------------------------------------
// tf32 mma helpers
// ---------------------------------------------------------------------------
__device__ __forceinline__ uint32_t f2tf32(float f) {
    uint32_t u;
    asm("cvt.rna.tf32.f32 %0, %1;" : "=r"(u) : "f"(f));
    return u;
}
__device__ __forceinline__ float f2tf32f(float f) {
    return __uint_as_float(f2tf32(f));
}
__device__ __forceinline__ void mma_tf32(float c[4], const uint32_t a[4],
                                         uint32_t b0, uint32_t b1) {
    asm volatile(
        "mma.sync.aligned.m16n8k8.row.col.f32.tf32.tf32.f32 "
        "{%0,%1,%2,%3}, {%4,%5,%6,%7}, {%8,%9}, {%0,%1,%2,%3};"
        : "+f"(c[0]), "+f"(c[1]), "+f"(c[2]), "+f"(c[3])
        : "r"(a[0]), "r"(a[1]), "r"(a[2]), "r"(a[3]), "r"(b0), "r"(b1));
}

__device__ __forceinline__ void cp_async16(uint32_t smem_addr, const void* gptr, int src_bytes) {
    asm volatile("cp.async.cg.shared.global [%0], [%1], 16, %2;"
                 :: "r"(smem_addr), "l"(gptr), "r"(src_bytes));
}
__device__ __forceinline__ void cp_commit() {
    asm volatile("cp.async.commit_group;" ::: "memory");
}

// ---------------------------------------------------------------------------
// Kernel 0: segment starts from sorted batch ids
// ---------------------------------------------------------------------------
__global__ void starts_kernel(const int* __restrict__ batch, int N) {
    int i = blockIdx.x * blockDim.x + threadIdx.x;
    if (i == 0) { g_starts[0] = 0; g_starts[NB] = N; }
    if (i > 0 && i < N && batch[i] != batch[i - 1]) g_starts[batch[i]] = i;
}

// ---------------------------------------------------------------------------
// tf32 tensor-core GEMM with register prefetch of the next K-chunk.
// C[M,256] = A[M,256] @ W[256,256] + bias ; MODE 1: C = A + relu(acc+bias)
// 128 threads, 64x64 block tile, BK=32, 4 warps in 2x2 (32x32 warp tiles).
// ---------------------------------------------------------------------------
template <int MODE>
__global__ __launch_bounds__(128)
void tgemm_kernel(const float* __restrict__ A,
                  const float* __restrict__ W,
                  const float* __restrict__ bias,
                  float* __restrict__ C, int M) {
    __shared__ float As[64][36];
    __shared__ float Ws[32][72];

    const int bm = blockIdx.x * 64;
    const int bn = blockIdx.y * 64;
    const int tid  = threadIdx.x;
    const int w    = tid >> 5;
    const int lane = tid & 31;
    const int g    = lane >> 2;
    const int m4   = lane & 3;
    const int wm   = (w >> 1) * 32;
    const int wn   = (w & 1) * 32;

    // per-thread load coordinates
    const int ra = tid >> 3, ca = (tid & 7) * 4;     // A: row stride 16 per i
    const int rw = tid >> 4, cw = (tid & 15) * 4;    // W: row stride 8 per i

    float4 pa[4], pw[4];

    auto load_tile = [&](int k0) {
#pragma unroll
        for (int i = 0; i < 4; i++) {
            int r = ra + i * 16;
            pa[i] = make_float4(0.f, 0.f, 0.f, 0.f);
            if (bm + r < M) pa[i] = *(const float4*)&A[(bm + r) * 256 + k0 + ca];
            int r2 = rw + i * 8;
            pw[i] = *(const float4*)&W[(k0 + r2) * 256 + bn + cw];
        }
    };
    auto store_tile = [&]() {
#pragma unroll
        for (int i = 0; i < 4; i++) {
            int r = ra + i * 16;
            As[r][ca + 0] = f2tf32f(pa[i].x);
            As[r][ca + 1] = f2tf32f(pa[i].y);
            As[r][ca + 2] = f2tf32f(pa[i].z);
            As[r][ca + 3] = f2tf32f(pa[i].w);
            int r2 = rw + i * 8;
            Ws[r2][cw + 0] = f2tf32f(pw[i].x);
            Ws[r2][cw + 1] = f2tf32f(pw[i].y);
            Ws[r2][cw + 2] = f2tf32f(pw[i].z);
            Ws[r2][cw + 3] = f2tf32f(pw[i].w);
        }
    };

    float acc[2][4][4];
#pragma unroll
    for (int mt = 0; mt < 2; mt++)
#pragma unroll
        for (int nt = 0; nt < 4; nt++)
#pragma unroll
            for (int j = 0; j < 4; j++) acc[mt][nt][j] = 0.f;

    load_tile(0);

#pragma unroll 1
    for (int kt = 0; kt < 8; kt++) {
        store_tile();
        __syncthreads();
        if (kt + 1 < 8) load_tile((kt + 1) * 32);   // LDGs overlap the mma below

#pragma unroll
        for (int k8 = 0; k8 < 4; k8++) {
            uint32_t a[2][4];
#pragma unroll
            for (int mt = 0; mt < 2; mt++) {
                int mr = wm + mt * 16;
                a[mt][0] = __float_as_uint(As[mr + g    ][k8 * 8 + m4]);
                a[mt][1] = __float_as_uint(As[mr + g + 8][k8 * 8 + m4]);
                a[mt][2] = __float_as_uint(As[mr + g    ][k8 * 8 + m4 + 4]);
                a[mt][3] = __float_as_uint(As[mr + g + 8][k8 * 8 + m4 + 4]);
            }
#pragma unroll
            for (int nt = 0; nt < 4; nt++) {
                uint32_t b0 = __float_as_uint(Ws[k8 * 8 + m4    ][wn + nt * 8 + g]);
                uint32_t b1 = __float_as_uint(Ws[k8 * 8 + m4 + 4][wn + nt * 8 + g]);
                mma_tf32(acc[0][nt], a[0], b0, b1);
                mma_tf32(acc[1][nt], a[1], b0, b1);
            }
        }
        __syncthreads();
    }

    // epilogue
#pragma unroll
    for (int mt = 0; mt < 2; mt++) {
#pragma unroll
        for (int i = 0; i < 2; i++) {
            int row = bm + wm + mt * 16 + g + i * 8;
            if (row >= M) continue;
#pragma unroll
            for (int nt = 0; nt < 4; nt++) {
                int col = bn + wn + nt * 8 + 2 * m4;
                float x = acc[mt][nt][i * 2 + 0] + bias[col];
                float y = acc[mt][nt][i * 2 + 1] + bias[col + 1];
                if (MODE == 1) {
                    float2 av = *(const float2*)&A[row * 256 + col];
                    x = av.x + fmaxf(x, 0.f);
                    y = av.y + fmaxf(y, 0.f);
                }
                *(float2*)&C[row * 256 + col] = make_float2(x, y);
            }
        }
    }
}

// ---------------------------------------------------------------------------
// Attention with tf32 tensor cores + cp.async double-buffered K/V pipeline.
// Block = (64-query tile, batch, head), 4 warps, each warp owns 16 queries.
// K/V enter mma as raw fp32 (HW tf32 truncation); Q and P stay RNA-rounded.
// ---------------------------------------------------------------------------
#define ATQ 64
__global__ void attn_kernel(float* __restrict__ att) {
    const int b = blockIdx.y;
    const int h = blockIdx.z;
    const int s0 = g_starts[b];
    const int L  = g_starts[b + 1] - s0;
    const int q0 = blockIdx.x * ATQ;
    if (q0 >= L) return;

    __shared__ __align__(16) float Ks[2][32][36];
    __shared__ __align__(16) float Vs[2][32][36];
    __shared__ float Ps[4][16][36];

    const int tid  = threadIdx.x;
    const int w    = tid >> 5;
    const int lane = tid & 31;
    const int g    = lane >> 2;
    const int m4   = lane & 3;

    const int q0w = q0 + w * 16;
    const float scale = 0.17677669529663687f;

    // cp.async issue for one 32-key chunk into buffer `buf`
    auto issue_kv = [&](int ci, int buf) {
#pragma unroll
        for (int s = 0; s < 2; s++) {
            int seg   = tid + s * 128;        // 0..255
            int row   = seg >> 3;             // 0..31
            int off16 = (seg & 7) * 16;       // byte offset in 128B row payload
            int kg    = ci * 32 + row;
            int ok    = (kg < L) ? 16 : 0;    // zero-fill out-of-range rows
            int kr    = (kg < L) ? kg : 0;
            const char* gk = (const char*)&g_kp[(s0 + kr) * 256 + h * 32] + off16;
            const char* gv = (const char*)&g_vp[(s0 + kr) * 256 + h * 32] + off16;
            uint32_t dk = (uint32_t)__cvta_generic_to_shared(&Ks[buf][row][0]) + off16;
            uint32_t dv = (uint32_t)__cvta_generic_to_shared(&Vs[buf][row][0]) + off16;
            cp_async16(dk, gk, ok);
            cp_async16(dv, gv, ok);
        }
    };

    // Q fragments, register-resident, pre-scaled, RNA-rounded
    uint32_t qa[4][4];
#pragma unroll
    for (int ks = 0; ks < 4; ks++) {
        int d0 = ks * 8 + m4;
        int r0 = q0w + g, r1 = q0w + g + 8;
        float v00 = (r0 < L) ? g_qp[(s0 + r0) * 256 + h * 32 + d0]     : 0.f;
        float v10 = (r1 < L) ? g_qp[(s0 + r1) * 256 + h * 32 + d0]     : 0.f;
        float v01 = (r0 < L) ? g_qp[(s0 + r0) * 256 + h * 32 + d0 + 4] : 0.f;
        float v11 = (r1 < L) ? g_qp[(s0 + r1) * 256 + h * 32 + d0 + 4] : 0.f;
        qa[ks][0] = f2tf32(v00 * scale);
        qa[ks][1] = f2tf32(v10 * scale);
        qa[ks][2] = f2tf32(v01 * scale);
        qa[ks][3] = f2tf32(v11 * scale);
    }

    float o[4][4];
#pragma unroll
    for (int i = 0; i < 4; i++)
#pragma unroll
        for (int j = 0; j < 4; j++) o[i][j] = 0.f;
    float m0 = -1e30f, m1 = -1e30f, l0 = 0.f, l1 = 0.f;

    const int nc = (L + 31) >> 5;

    issue_kv(0, 0);
    cp_commit();

#pragma unroll 1
    for (int ci = 0; ci < nc; ci++) {
        const int buf = ci & 1;
        const int kc  = ci * 32;
        if (ci + 1 < nc) {
            issue_kv(ci + 1, buf ^ 1);
            cp_commit();
            asm volatile("cp.async.wait_group 1;" ::: "memory");
        } else {
            asm volatile("cp.async.wait_group 0;" ::: "memory");
        }
        __syncthreads();

        // ---- QK^T: S[16][32] per warp ----
        float sc[4][4];
#pragma unroll
        for (int nt = 0; nt < 4; nt++)
#pragma unroll
            for (int j = 0; j < 4; j++) sc[nt][j] = 0.f;
#pragma unroll
        for (int ks = 0; ks < 4; ks++) {
#pragma unroll
            for (int nt = 0; nt < 4; nt++) {
                uint32_t b0 = __float_as_uint(Ks[buf][nt * 8 + g][ks * 8 + m4]);
                uint32_t b1 = __float_as_uint(Ks[buf][nt * 8 + g][ks * 8 + m4 + 4]);
                mma_tf32(sc[nt], qa[ks], b0, b1);
            }
        }

        // ---- mask + online softmax ----
        float mx0 = -1e30f, mx1 = -1e30f;
#pragma unroll
        for (int nt = 0; nt < 4; nt++) {
            int kcol0 = kc + nt * 8 + 2 * m4;
            if (kcol0 >= L)     { sc[nt][0] = -1e30f; sc[nt][2] = -1e30f; }
            if (kcol0 + 1 >= L) { sc[nt][1] = -1e30f; sc[nt][3] = -1e30f; }
            mx0 = fmaxf(mx0, fmaxf(sc[nt][0], sc[nt][1]));
            mx1 = fmaxf(mx1, fmaxf(sc[nt][2], sc[nt][3]));
        }
        mx0 = fmaxf(mx0, __shfl_xor_sync(0xffffffffu, mx0, 1));
        mx0 = fmaxf(mx0, __shfl_xor_sync(0xffffffffu, mx0, 2));
        mx1 = fmaxf(mx1, __shfl_xor_sync(0xffffffffu, mx1, 1));
        mx1 = fmaxf(mx1, __shfl_xor_sync(0xffffffffu, mx1, 2));

        float m0n = fmaxf(m0, mx0);
        float m1n = fmaxf(m1, mx1);
        float c0 = __expf(m0 - m0n);
        float c1 = __expf(m1 - m1n);
        m0 = m0n; m1 = m1n;

        float s0r = 0.f, s1r = 0.f;
#pragma unroll
        for (int nt = 0; nt < 4; nt++) {
            float p00 = __expf(sc[nt][0] - m0n);
            float p01 = __expf(sc[nt][1] - m0n);
            float p10 = __expf(sc[nt][2] - m1n);
            float p11 = __expf(sc[nt][3] - m1n);
            s0r += p00 + p01;
            s1r += p10 + p11;
            int col = nt * 8 + 2 * m4;
            Ps[w][g][col]         = f2tf32f(p00);
            Ps[w][g][col + 1]     = f2tf32f(p01);
            Ps[w][g + 8][col]     = f2tf32f(p10);
            Ps[w][g + 8][col + 1] = f2tf32f(p11);
        }
        s0r += __shfl_xor_sync(0xffffffffu, s0r, 1);
        s0r += __shfl_xor_sync(0xffffffffu, s0r, 2);
        s1r += __shfl_xor_sync(0xffffffffu, s1r, 1);
        s1r += __shfl_xor_sync(0xffffffffu, s1r, 2);
        l0 = l0 * c0 + s0r;
        l1 = l1 * c1 + s1r;

#pragma unroll
        for (int nt = 0; nt < 4; nt++) {
            o[nt][0] *= c0; o[nt][1] *= c0;
            o[nt][2] *= c1; o[nt][3] *= c1;
        }

        __syncwarp();

        // ---- PV: O[16][32] += P[16][32] @ V[32][32] ----
#pragma unroll
        for (int ks = 0; ks < 4; ks++) {
            uint32_t pa[4];
            pa[0] = __float_as_uint(Ps[w][g][ks * 8 + m4]);
            pa[1] = __float_as_uint(Ps[w][g + 8][ks * 8 + m4]);
            pa[2] = __float_as_uint(Ps[w][g][ks * 8 + m4 + 4]);
            pa[3] = __float_as_uint(Ps[w][g + 8][ks * 8 + m4 + 4]);
#pragma unroll
            for (int nt = 0; nt < 4; nt++) {
                uint32_t b0 = __float_as_uint(Vs[buf][ks * 8 + m4][nt * 8 + g]);
                uint32_t b1 = __float_as_uint(Vs[buf][ks * 8 + m4 + 4][nt * 8 + g]);
                mma_tf32(o[nt], pa, b0, b1);
            }
        }
        __syncthreads();   // protect buf from the issue two iterations ahead
    }

    // ---- epilogue: normalize, residual +qp, store ----
    float il0 = 1.f / l0, il1 = 1.f / l1;
    int r0 = q0w + g, r1 = q0w + g + 8;
#pragma unroll
    for (int nt = 0; nt < 4; nt++) {
        int dh = nt * 8 + 2 * m4;
        if (r0 < L) {
            int base = (s0 + r0) * 256 + h * 32 + dh;
            float2 qv = *(const float2*)&g_qp[base];
            float2 ov = make_float2(o[nt][0] * il0 + qv.x, o[nt][1] * il0 + qv.y);
            *(float2*)&att[base] = ov;
        }
        if (r1 < L) {
            int base = (s0 + r1) * 256 + h * 32 + dh;
            float2 qv = *(const float2*)&g_qp[base];
            float2 ov = make_float2(o[nt][2] * il1 + qv.x, o[nt][3] * il1 + qv.y);
            *(float2*)&att[base] = ov;
        }
    }
}

// ---------------------------------------------------------------------------
// Launch
// ---------------------------------------------------------------------------
extern "C" void kernel_launch(void* const* d_in, const int* in_sizes, int n_in,
                              void* d_out, int out_size) {
    const float* q   = (const float*)d_in[0];
    const float* k   = (const float*)d_in[1];
    const int* batch_q = (const int*)d_in[2];
    const float* Wq = (const float*)d_in[4];
    const float* bq = (const float*)d_in[5];
    const float* Wk = (const float*)d_in[6];
    const float* bk = (const float*)d_in[7];
    const float* Wv = (const float*)d_in[8];
    const float* bv = (const float*)d_in[9];
    const float* Wo = (const float*)d_in[10];
    const float* bo = (const float*)d_in[11];
    float* out = (float*)d_out;

    const int N = in_sizes[0] / 256;

    float* qp;  cudaGetSymbolAddress((void**)&qp,  g_qp);
    float* kp;  cudaGetSymbolAddress((void**)&kp,  g_kp);
    float* vp;  cudaGetSymbolAddress((void**)&vp,  g_vp);
    float* att; cudaGetSymbolAddress((void**)&att, g_att);

    starts_kernel<<<(N + 255) / 256, 256>>>(batch_q, N);

    dim3 ggrid((N + 63) / 64, 4);
    tgemm_kernel<0><<<ggrid, 128>>>(q, Wq, bq, qp, N);
    tgemm_kernel<0><<<ggrid, 128>>>(k, Wk, bk, kp, N);
    tgemm_kernel<0><<<ggrid, 128>>>(k, Wv, bv, vp, N);

    dim3 agrid(1024 / ATQ, NB, 8);
    attn_kernel<<<agrid, 128>>>(att);

    tgemm_kernel<1><<<ggrid, 128>>>(att, Wo, bo, out, N);
}

// round 10
// speedup vs baseline: 4.6025x; 1.0559x over previous
#include <cuda_runtime.h>
#include <cstdint>

// Problem constants: B=16, MAX_LEN=1024, DV=256, H=8, DH=32
#define NB 16
#define DVC 256
#define MAXN 12160

// Device scratch (allocation-free requirement)
__device__ float g_qp[MAXN * DVC];
__device__ float g_kp[MAXN * DVC];
__device__ float g_vp[MAXN * DVC];
__device__ float g_att[MAXN * DVC];
__device__ int   g_starts[NB + 1];

// ---------------------------------------------------------------------------
// tf32 mma helpers
// ---------------------------------------------------------------------------
__device__ __forceinline__ uint32_t f2tf32(float f) {
    uint32_t u;
    asm("cvt.rna.tf32.f32 %0, %1;" : "=r"(u) : "f"(f));
    return u;
}
__device__ __forceinline__ float f2tf32f(float f) {
    return __uint_as_float(f2tf32(f));
}
__device__ __forceinline__ void mma_tf32(float c[4], const uint32_t a[4],
                                         uint32_t b0, uint32_t b1) {
    asm volatile(
        "mma.sync.aligned.m16n8k8.row.col.f32.tf32.tf32.f32 "
        "{%0,%1,%2,%3}, {%4,%5,%6,%7}, {%8,%9}, {%0,%1,%2,%3};"
        : "+f"(c[0]), "+f"(c[1]), "+f"(c[2]), "+f"(c[3])
        : "r"(a[0]), "r"(a[1]), "r"(a[2]), "r"(a[3]), "r"(b0), "r"(b1));
}

__device__ __forceinline__ void cp_async16(uint32_t smem_addr, const void* gptr, int src_bytes) {
    asm volatile("cp.async.cg.shared.global [%0], [%1], 16, %2;"
                 :: "r"(smem_addr), "l"(gptr), "r"(src_bytes));
}
__device__ __forceinline__ void cp_commit() {
    asm volatile("cp.async.commit_group;" ::: "memory");
}

// ---------------------------------------------------------------------------
// Kernel 0: segment starts from sorted batch ids
// ---------------------------------------------------------------------------
__global__ void starts_kernel(const int* __restrict__ batch, int N) {
    int i = blockIdx.x * blockDim.x + threadIdx.x;
    if (i == 0) { g_starts[0] = 0; g_starts[NB] = N; }
    if (i > 0 && i < N && batch[i] != batch[i - 1]) g_starts[batch[i]] = i;
}

// ---------------------------------------------------------------------------
// tf32 GEMM body — round-5 proven staging (LDG float4 -> STS, single buffer),
// NO cp.async, NO explicit tf32 cvt (raw fp32 into mma; HW rounds — validated
// round 7: +3e-7 rel_err).
// C[bm:bm+64, bn:bn+64] = A[.,256] @ W[256,.] + bias ; MODE 1: A + relu(.)
// 128 threads, BK=32, 4 warps in 2x2 (32x32 warp tiles).
// Conflict-free fragment reads: As[64][36] (bank=4g+m4), Ws[32][72] (bank=8m4+g).
// ---------------------------------------------------------------------------
template <int MODE>
__device__ __forceinline__ void gemm_body(
    const float* __restrict__ A, const float* __restrict__ W,
    const float* __restrict__ bias, float* __restrict__ C,
    int bm, int bn, int M,
    float (&As)[64][36], float (&Ws)[32][72])
{
    const int tid  = threadIdx.x;
    const int w    = tid >> 5;
    const int lane = tid & 31;
    const int g    = lane >> 2;
    const int m4   = lane & 3;
    const int wm   = (w >> 1) * 32;
    const int wn   = (w & 1) * 32;

    float acc[2][4][4];
#pragma unroll
    for (int mt = 0; mt < 2; mt++)
#pragma unroll
        for (int nt = 0; nt < 4; nt++)
#pragma unroll
            for (int j = 0; j < 4; j++) acc[mt][nt][j] = 0.f;

#pragma unroll 1
    for (int k0 = 0; k0 < 256; k0 += 32) {
        // A tile 64x32 (raw fp32)
#pragma unroll
        for (int i = 0; i < 4; i++) {
            int s = tid + i * 128;
            int r = s >> 3, c = (s & 7) * 4;
            float4 v = make_float4(0.f, 0.f, 0.f, 0.f);
            if (bm + r < M) v = *(const float4*)&A[(bm + r) * 256 + k0 + c];
            As[r][c + 0] = v.x;
            As[r][c + 1] = v.y;
            As[r][c + 2] = v.z;
            As[r][c + 3] = v.w;
        }
        // W tile 32x64
#pragma unroll
        for (int i = 0; i < 4; i++) {
            int s = tid + i * 128;
            int r = s >> 4, c = (s & 15) * 4;
            float4 v = *(const float4*)&W[(k0 + r) * 256 + bn + c];
            Ws[r][c + 0] = v.x;
            Ws[r][c + 1] = v.y;
            Ws[r][c + 2] = v.z;
            Ws[r][c + 3] = v.w;
        }
        __syncthreads();

#pragma unroll
        for (int k8 = 0; k8 < 4; k8++) {
            uint32_t a[2][4];
#pragma unroll
            for (int mt = 0; mt < 2; mt++) {
                int mr = wm + mt * 16;
                a[mt][0] = __float_as_uint(As[mr + g    ][k8 * 8 + m4]);
                a[mt][1] = __float_as_uint(As[mr + g + 8][k8 * 8 + m4]);
                a[mt][2] = __float_as_uint(As[mr + g    ][k8 * 8 + m4 + 4]);
                a[mt][3] = __float_as_uint(As[mr + g + 8][k8 * 8 + m4 + 4]);
            }
#pragma unroll
            for (int nt = 0; nt < 4; nt++) {
                uint32_t b0 = __float_as_uint(Ws[k8 * 8 + m4    ][wn + nt * 8 + g]);
                uint32_t b1 = __float_as_uint(Ws[k8 * 8 + m4 + 4][wn + nt * 8 + g]);
                mma_tf32(acc[0][nt], a[0], b0, b1);
                mma_tf32(acc[1][nt], a[1], b0, b1);
            }
        }
        __syncthreads();
    }

    // epilogue
#pragma unroll
    for (int mt = 0; mt < 2; mt++) {
#pragma unroll
        for (int i = 0; i < 2; i++) {
            int row = bm + wm + mt * 16 + g + i * 8;
            if (row >= M) continue;
#pragma unroll
            for (int nt = 0; nt < 4; nt++) {
                int col = bn + wn + nt * 8 + 2 * m4;
                float x = acc[mt][nt][i * 2 + 0] + bias[col];
                float y = acc[mt][nt][i * 2 + 1] + bias[col + 1];
                if (MODE == 1) {
                    float2 av = *(const float2*)&A[row * 256 + col];
                    x = av.x + fmaxf(x, 0.f);
                    y = av.y + fmaxf(y, 0.f);
                }
                *(float2*)&C[row * 256 + col] = make_float2(x, y);
            }
        }
    }
}

// ---------------------------------------------------------------------------
// Fused projection kernel: one launch computes qp, kp, vp.
// grid = (ceil(N/64), 12); blockIdx.y selects {matrix, 64-col slab}.
// ---------------------------------------------------------------------------
__global__ __launch_bounds__(128) void proj_kernel(
    const float* __restrict__ q, const float* __restrict__ k,
    const float* __restrict__ Wq, const float* __restrict__ bq,
    const float* __restrict__ Wk, const float* __restrict__ bk,
    const float* __restrict__ Wv, const float* __restrict__ bv,
    float* __restrict__ qp, float* __restrict__ kp, float* __restrict__ vp,
    int M)
{
    __shared__ float As[64][36];
    __shared__ float Ws[32][72];

    const int by  = blockIdx.y;
    const int sel = by >> 2;
    const float* A    = (sel == 0) ? q  : k;
    const float* W    = (sel == 0) ? Wq : (sel == 1) ? Wk : Wv;
    const float* bias = (sel == 0) ? bq : (sel == 1) ? bk : bv;
    float* C          = (sel == 0) ? qp : (sel == 1) ? kp : vp;
    const int bn = (by & 3) * 64;

    gemm_body<0>(A, W, bias, C, blockIdx.x * 64, bn, M, As, Ws);
}

// Output GEMM with fused residual + ReLU epilogue.
__global__ __launch_bounds__(128) void outgemm_kernel(
    const float* __restrict__ A, const float* __restrict__ W,
    const float* __restrict__ bias, float* __restrict__ C, int M)
{
    __shared__ float As[64][36];
    __shared__ float Ws[32][72];
    gemm_body<1>(A, W, bias, C, blockIdx.x * 64, blockIdx.y * 64, M, As, Ws);
}

// ---------------------------------------------------------------------------
// Attention with tf32 tensor cores + cp.async double-buffered K/V pipeline.
// (byte-identical to round 7's passing kernel, measured ~131 us)
// ---------------------------------------------------------------------------
#define ATQ 64
__global__ void attn_kernel(float* __restrict__ att) {
    const int b = blockIdx.y;
    const int h = blockIdx.z;
    const int s0 = g_starts[b];
    const int L  = g_starts[b + 1] - s0;
    const int q0 = blockIdx.x * ATQ;
    if (q0 >= L) return;

    __shared__ __align__(16) float Ks[2][32][36];
    __shared__ __align__(16) float Vs[2][32][36];
    __shared__ float Ps[4][16][36];

    const int tid  = threadIdx.x;
    const int w    = tid >> 5;
    const int lane = tid & 31;
    const int g    = lane >> 2;
    const int m4   = lane & 3;

    const int q0w = q0 + w * 16;
    const float scale = 0.17677669529663687f;

    auto issue_kv = [&](int ci, int buf) {
#pragma unroll
        for (int s = 0; s < 2; s++) {
            int seg   = tid + s * 128;
            int row   = seg >> 3;
            int off16 = (seg & 7) * 16;
            int kg    = ci * 32 + row;
            int ok    = (kg < L) ? 16 : 0;
            int kr    = (kg < L) ? kg : 0;
            const char* gk = (const char*)&g_kp[(s0 + kr) * 256 + h * 32] + off16;
            const char* gv = (const char*)&g_vp[(s0 + kr) * 256 + h * 32] + off16;
            uint32_t dk = (uint32_t)__cvta_generic_to_shared(&Ks[buf][row][0]) + off16;
            uint32_t dv = (uint32_t)__cvta_generic_to_shared(&Vs[buf][row][0]) + off16;
            cp_async16(dk, gk, ok);
            cp_async16(dv, gv, ok);
        }
    };

    uint32_t qa[4][4];
#pragma unroll
    for (int ks = 0; ks < 4; ks++) {
        int d0 = ks * 8 + m4;
        int r0 = q0w + g, r1 = q0w + g + 8;
        float v00 = (r0 < L) ? g_qp[(s0 + r0) * 256 + h * 32 + d0]     : 0.f;
        float v10 = (r1 < L) ? g_qp[(s0 + r1) * 256 + h * 32 + d0]     : 0.f;
        float v01 = (r0 < L) ? g_qp[(s0 + r0) * 256 + h * 32 + d0 + 4] : 0.f;
        float v11 = (r1 < L) ? g_qp[(s0 + r1) * 256 + h * 32 + d0 + 4] : 0.f;
        qa[ks][0] = f2tf32(v00 * scale);
        qa[ks][1] = f2tf32(v10 * scale);
        qa[ks][2] = f2tf32(v01 * scale);
        qa[ks][3] = f2tf32(v11 * scale);
    }

    float o[4][4];
#pragma unroll
    for (int i = 0; i < 4; i++)
#pragma unroll
        for (int j = 0; j < 4; j++) o[i][j] = 0.f;
    float m0 = -1e30f, m1 = -1e30f, l0 = 0.f, l1 = 0.f;

    const int nc = (L + 31) >> 5;

    issue_kv(0, 0);
    cp_commit();

#pragma unroll 1
    for (int ci = 0; ci < nc; ci++) {
        const int buf = ci & 1;
        const int kc  = ci * 32;
        if (ci + 1 < nc) {
            issue_kv(ci + 1, buf ^ 1);
            cp_commit();
            asm volatile("cp.async.wait_group 1;" ::: "memory");
        } else {
            asm volatile("cp.async.wait_group 0;" ::: "memory");
        }
        __syncthreads();

        float sc[4][4];
#pragma unroll
        for (int nt = 0; nt < 4; nt++)
#pragma unroll
            for (int j = 0; j < 4; j++) sc[nt][j] = 0.f;
#pragma unroll
        for (int ks = 0; ks < 4; ks++) {
#pragma unroll
            for (int nt = 0; nt < 4; nt++) {
                uint32_t b0 = __float_as_uint(Ks[buf][nt * 8 + g][ks * 8 + m4]);
                uint32_t b1 = __float_as_uint(Ks[buf][nt * 8 + g][ks * 8 + m4 + 4]);
                mma_tf32(sc[nt], qa[ks], b0, b1);
            }
        }

        float mx0 = -1e30f, mx1 = -1e30f;
#pragma unroll
        for (int nt = 0; nt < 4; nt++) {
            int kcol0 = kc + nt * 8 + 2 * m4;
            if (kcol0 >= L)     { sc[nt][0] = -1e30f; sc[nt][2] = -1e30f; }
            if (kcol0 + 1 >= L) { sc[nt][1] = -1e30f; sc[nt][3] = -1e30f; }
            mx0 = fmaxf(mx0, fmaxf(sc[nt][0], sc[nt][1]));
            mx1 = fmaxf(mx1, fmaxf(sc[nt][2], sc[nt][3]));
        }
        mx0 = fmaxf(mx0, __shfl_xor_sync(0xffffffffu, mx0, 1));
        mx0 = fmaxf(mx0, __shfl_xor_sync(0xffffffffu, mx0, 2));
        mx1 = fmaxf(mx1, __shfl_xor_sync(0xffffffffu, mx1, 1));
        mx1 = fmaxf(mx1, __shfl_xor_sync(0xffffffffu, mx1, 2));

        float m0n = fmaxf(m0, mx0);
        float m1n = fmaxf(m1, mx1);
        float c0 = __expf(m0 - m0n);
        float c1 = __expf(m1 - m1n);
        m0 = m0n; m1 = m1n;

        float s0r = 0.f, s1r = 0.f;
#pragma unroll
        for (int nt = 0; nt < 4; nt++) {
            float p00 = __expf(sc[nt][0] - m0n);
            float p01 = __expf(sc[nt][1] - m0n);
            float p10 = __expf(sc[nt][2] - m1n);
            float p11 = __expf(sc[nt][3] - m1n);
            s0r += p00 + p01;
            s1r += p10 + p11;
            int col = nt * 8 + 2 * m4;
            Ps[w][g][col]         = f2tf32f(p00);
            Ps[w][g][col + 1]     = f2tf32f(p01);
            Ps[w][g + 8][col]     = f2tf32f(p10);
            Ps[w][g + 8][col + 1] = f2tf32f(p11);
        }
        s0r += __shfl_xor_sync(0xffffffffu, s0r, 1);
        s0r += __shfl_xor_sync(0xffffffffu, s0r, 2);
        s1r += __shfl_xor_sync(0xffffffffu, s1r, 1);
        s1r += __shfl_xor_sync(0xffffffffu, s1r, 2);
        l0 = l0 * c0 + s0r;
        l1 = l1 * c1 + s1r;

#pragma unroll
        for (int nt = 0; nt < 4; nt++) {
            o[nt][0] *= c0; o[nt][1] *= c0;
            o[nt][2] *= c1; o[nt][3] *= c1;
        }

        __syncwarp();

#pragma unroll
        for (int ks = 0; ks < 4; ks++) {
            uint32_t pa[4];
            pa[0] = __float_as_uint(Ps[w][g][ks * 8 + m4]);
            pa[1] = __float_as_uint(Ps[w][g + 8][ks * 8 + m4]);
            pa[2] = __float_as_uint(Ps[w][g][ks * 8 + m4 + 4]);
            pa[3] = __float_as_uint(Ps[w][g + 8][ks * 8 + m4 + 4]);
#pragma unroll
            for (int nt = 0; nt < 4; nt++) {
                uint32_t b0 = __float_as_uint(Vs[buf][ks * 8 + m4][nt * 8 + g]);
                uint32_t b1 = __float_as_uint(Vs[buf][ks * 8 + m4 + 4][nt * 8 + g]);
                mma_tf32(o[nt], pa, b0, b1);
            }
        }
        __syncthreads();
    }

    float il0 = 1.f / l0, il1 = 1.f / l1;
    int r0 = q0w + g, r1 = q0w + g + 8;
#pragma unroll
    for (int nt = 0; nt < 4; nt++) {
        int dh = nt * 8 + 2 * m4;
        if (r0 < L) {
            int base = (s0 + r0) * 256 + h * 32 + dh;
            float2 qv = *(const float2*)&g_qp[base];
            float2 ov = make_float2(o[nt][0] * il0 + qv.x, o[nt][1] * il0 + qv.y);
            *(float2*)&att[base] = ov;
        }
        if (r1 < L) {
            int base = (s0 + r1) * 256 + h * 32 + dh;
            float2 qv = *(const float2*)&g_qp[base];
            float2 ov = make_float2(o[nt][2] * il1 + qv.x, o[nt][3] * il1 + qv.y);
            *(float2*)&att[base] = ov;
        }
    }
}

// ---------------------------------------------------------------------------
// Launch
// ---------------------------------------------------------------------------
extern "C" void kernel_launch(void* const* d_in, const int* in_sizes, int n_in,
                              void* d_out, int out_size) {
    const float* q   = (const float*)d_in[0];
    const float* k   = (const float*)d_in[1];
    const int* batch_q = (const int*)d_in[2];
    const float* Wq = (const float*)d_in[4];
    const float* bq = (const float*)d_in[5];
    const float* Wk = (const float*)d_in[6];
    const float* bk = (const float*)d_in[7];
    const float* Wv = (const float*)d_in[8];
    const float* bv = (const float*)d_in[9];
    const float* Wo = (const float*)d_in[10];
    const float* bo = (const float*)d_in[11];
    float* out = (float*)d_out;

    const int N = in_sizes[0] / 256;

    float* qp;  cudaGetSymbolAddress((void**)&qp,  g_qp);
    float* kp;  cudaGetSymbolAddress((void**)&kp,  g_kp);
    float* vp;  cudaGetSymbolAddress((void**)&vp,  g_vp);
    float* att; cudaGetSymbolAddress((void**)&att, g_att);

    starts_kernel<<<(N + 255) / 256, 256>>>(batch_q, N);

    dim3 pgrid((N + 63) / 64, 12);
    proj_kernel<<<pgrid, 128>>>(q, k, Wq, bq, Wk, bk, Wv, bv, qp, kp, vp, N);

    dim3 agrid(1024 / ATQ, NB, 8);
    attn_kernel<<<agrid, 128>>>(att);

    dim3 ogrid((N + 63) / 64, 4);
    outgemm_kernel<<<ogrid, 128>>>(att, Wo, bo, out, N);
}

// round 11
// speedup vs baseline: 6.6101x; 1.4362x over previous
#include <cuda_runtime.h>
#include <cstdint>

// Problem constants: B=16, MAX_LEN=1024, DV=256, H=8, DH=32
#define NB 16
#define DVC 256
#define MAXN 12160

// Device scratch (allocation-free requirement)
__device__ float    g_qp  [MAXN * DVC];
__device__ uint16_t g_kp16[MAXN * DVC];   // bf16 projected K
__device__ uint16_t g_vp16[MAXN * DVC];   // bf16 projected V
__device__ float    g_att [MAXN * DVC];
__device__ int      g_starts[NB + 1];

// ---------------------------------------------------------------------------
// helpers
// ---------------------------------------------------------------------------
__device__ __forceinline__ float f2tf32f(float f) {
    uint32_t u;
    asm("cvt.rna.tf32.f32 %0, %1;" : "=r"(u) : "f"(f));
    return __uint_as_float(u);
}
__device__ __forceinline__ void mma_tf32(float c[4], const uint32_t a[4],
                                         uint32_t b0, uint32_t b1) {
    asm volatile(
        "mma.sync.aligned.m16n8k8.row.col.f32.tf32.tf32.f32 "
        "{%0,%1,%2,%3}, {%4,%5,%6,%7}, {%8,%9}, {%0,%1,%2,%3};"
        : "+f"(c[0]), "+f"(c[1]), "+f"(c[2]), "+f"(c[3])
        : "r"(a[0]), "r"(a[1]), "r"(a[2]), "r"(a[3]), "r"(b0), "r"(b1));
}
__device__ __forceinline__ void mma_bf16(float c[4], const uint32_t a[4],
                                         uint32_t b0, uint32_t b1) {
    asm volatile(
        "mma.sync.aligned.m16n8k16.row.col.f32.bf16.bf16.f32 "
        "{%0,%1,%2,%3}, {%4,%5,%6,%7}, {%8,%9}, {%0,%1,%2,%3};"
        : "+f"(c[0]), "+f"(c[1]), "+f"(c[2]), "+f"(c[3])
        : "r"(a[0]), "r"(a[1]), "r"(a[2]), "r"(a[3]), "r"(b0), "r"(b1));
}
// pack (lo, hi) floats into bf16x2 (round-to-nearest)
__device__ __forceinline__ uint32_t bf16pk(float lo, float hi) {
    uint32_t r;
    asm("cvt.rn.bf16x2.f32 %0, %1, %2;" : "=r"(r) : "f"(hi), "f"(lo));
    return r;
}
__device__ __forceinline__ float ex2(float x) {
    float y; asm("ex2.approx.ftz.f32 %0, %1;" : "=f"(y) : "f"(x)); return y;
}
__device__ __forceinline__ void cp_async16(uint32_t smem_addr, const void* gptr, int src_bytes) {
    asm volatile("cp.async.cg.shared.global [%0], [%1], 16, %2;"
                 :: "r"(smem_addr), "l"(gptr), "r"(src_bytes));
}
__device__ __forceinline__ void cp_commit() {
    asm volatile("cp.async.commit_group;" ::: "memory");
}
__device__ __forceinline__ void ldsm_x4(uint32_t r[4], uint32_t addr) {
    asm volatile("ldmatrix.sync.aligned.m8n8.x4.shared.b16 {%0,%1,%2,%3}, [%4];"
                 : "=r"(r[0]), "=r"(r[1]), "=r"(r[2]), "=r"(r[3]) : "r"(addr));
}
__device__ __forceinline__ void ldsm_x4_t(uint32_t r[4], uint32_t addr) {
    asm volatile("ldmatrix.sync.aligned.m8n8.x4.trans.shared.b16 {%0,%1,%2,%3}, [%4];"
                 : "=r"(r[0]), "=r"(r[1]), "=r"(r[2]), "=r"(r[3]) : "r"(addr));
}

// ---------------------------------------------------------------------------
// Kernel 0: segment starts from sorted batch ids
// ---------------------------------------------------------------------------
__global__ void starts_kernel(const int* __restrict__ batch, int N) {
    int i = blockIdx.x * blockDim.x + threadIdx.x;
    if (i == 0) { g_starts[0] = 0; g_starts[NB] = N; }
    if (i > 0 && i < N && batch[i] != batch[i - 1]) g_starts[batch[i]] = i;
}

// ---------------------------------------------------------------------------
// tf32 GEMM body (round-5 proven staging, RNA tf32 rounding RESTORED).
// MODE 0: f32 out.  MODE 1: Cf = A + relu(acc+bias).  MODE 2: bf16 out (C16).
// ---------------------------------------------------------------------------
template <int MODE>
__device__ __forceinline__ void gemm_body(
    const float* __restrict__ A, const float* __restrict__ W,
    const float* __restrict__ bias, float* __restrict__ Cf,
    uint16_t* __restrict__ C16,
    int bm, int bn, int M,
    float (&As)[64][36], float (&Ws)[32][72])
{
    const int tid  = threadIdx.x;
    const int w    = tid >> 5;
    const int lane = tid & 31;
    const int g    = lane >> 2;
    const int m4   = lane & 3;
    const int wm   = (w >> 1) * 32;
    const int wn   = (w & 1) * 32;

    float acc[2][4][4];
#pragma unroll
    for (int mt = 0; mt < 2; mt++)
#pragma unroll
        for (int nt = 0; nt < 4; nt++)
#pragma unroll
            for (int j = 0; j < 4; j++) acc[mt][nt][j] = 0.f;

#pragma unroll 1
    for (int k0 = 0; k0 < 256; k0 += 32) {
#pragma unroll
        for (int i = 0; i < 4; i++) {
            int s = tid + i * 128;
            int r = s >> 3, c = (s & 7) * 4;
            float4 v = make_float4(0.f, 0.f, 0.f, 0.f);
            if (bm + r < M) v = *(const float4*)&A[(bm + r) * 256 + k0 + c];
            As[r][c + 0] = f2tf32f(v.x);
            As[r][c + 1] = f2tf32f(v.y);
            As[r][c + 2] = f2tf32f(v.z);
            As[r][c + 3] = f2tf32f(v.w);
        }
#pragma unroll
        for (int i = 0; i < 4; i++) {
            int s = tid + i * 128;
            int r = s >> 4, c = (s & 15) * 4;
            float4 v = *(const float4*)&W[(k0 + r) * 256 + bn + c];
            Ws[r][c + 0] = f2tf32f(v.x);
            Ws[r][c + 1] = f2tf32f(v.y);
            Ws[r][c + 2] = f2tf32f(v.z);
            Ws[r][c + 3] = f2tf32f(v.w);
        }
        __syncthreads();

#pragma unroll
        for (int k8 = 0; k8 < 4; k8++) {
            uint32_t a[2][4];
#pragma unroll
            for (int mt = 0; mt < 2; mt++) {
                int mr = wm + mt * 16;
                a[mt][0] = __float_as_uint(As[mr + g    ][k8 * 8 + m4]);
                a[mt][1] = __float_as_uint(As[mr + g + 8][k8 * 8 + m4]);
                a[mt][2] = __float_as_uint(As[mr + g    ][k8 * 8 + m4 + 4]);
                a[mt][3] = __float_as_uint(As[mr + g + 8][k8 * 8 + m4 + 4]);
            }
#pragma unroll
            for (int nt = 0; nt < 4; nt++) {
                uint32_t b0 = __float_as_uint(Ws[k8 * 8 + m4    ][wn + nt * 8 + g]);
                uint32_t b1 = __float_as_uint(Ws[k8 * 8 + m4 + 4][wn + nt * 8 + g]);
                mma_tf32(acc[0][nt], a[0], b0, b1);
                mma_tf32(acc[1][nt], a[1], b0, b1);
            }
        }
        __syncthreads();
    }

#pragma unroll
    for (int mt = 0; mt < 2; mt++) {
#pragma unroll
        for (int i = 0; i < 2; i++) {
            int row = bm + wm + mt * 16 + g + i * 8;
            if (row >= M) continue;
#pragma unroll
            for (int nt = 0; nt < 4; nt++) {
                int col = bn + wn + nt * 8 + 2 * m4;
                float x = acc[mt][nt][i * 2 + 0] + bias[col];
                float y = acc[mt][nt][i * 2 + 1] + bias[col + 1];
                if (MODE == 2) {
                    *(uint32_t*)&C16[row * 256 + col] = bf16pk(x, y);
                } else {
                    if (MODE == 1) {
                        float2 av = *(const float2*)&A[row * 256 + col];
                        x = av.x + fmaxf(x, 0.f);
                        y = av.y + fmaxf(y, 0.f);
                    }
                    *(float2*)&Cf[row * 256 + col] = make_float2(x, y);
                }
            }
        }
    }
}

// ---------------------------------------------------------------------------
// Fused projections: qp (f32), kp16/vp16 (bf16) in one launch.
// grid = (ceil(N/64), 12); blockIdx.y selects {matrix, 64-col slab}.
// ---------------------------------------------------------------------------
__global__ __launch_bounds__(128) void proj_kernel(
    const float* __restrict__ q, const float* __restrict__ k,
    const float* __restrict__ Wq, const float* __restrict__ bq,
    const float* __restrict__ Wk, const float* __restrict__ bk,
    const float* __restrict__ Wv, const float* __restrict__ bv,
    int M)
{
    __shared__ float As[64][36];
    __shared__ float Ws[32][72];

    const int by  = blockIdx.y;
    const int sel = by >> 2;
    const int bn  = (by & 3) * 64;
    const int bm  = blockIdx.x * 64;

    if (sel == 0)
        gemm_body<0>(q, Wq, bq, g_qp, nullptr, bm, bn, M, As, Ws);
    else if (sel == 1)
        gemm_body<2>(k, Wk, bk, nullptr, g_kp16, bm, bn, M, As, Ws);
    else
        gemm_body<2>(k, Wv, bv, nullptr, g_vp16, bm, bn, M, As, Ws);
}

// Output GEMM with fused residual + ReLU epilogue.
__global__ __launch_bounds__(128) void outgemm_kernel(
    const float* __restrict__ A, const float* __restrict__ W,
    const float* __restrict__ bias, float* __restrict__ C, int M)
{
    __shared__ float As[64][36];
    __shared__ float Ws[32][72];
    gemm_body<1>(A, W, bias, C, nullptr, blockIdx.x * 64, blockIdx.y * 64, M, As, Ws);
}

// ---------------------------------------------------------------------------
// bf16 flash attention. Block = (64-q tile, batch, head), 4 warps x 16 q.
// m16n8k16 bf16 mma; QK C-fragment == PV A-fragment (no P smem roundtrip).
// K B-frags via ldmatrix.x4; V B-frags via ldmatrix.x4.trans.
// Softmax in log2 domain (log2e folded into Q scale), ex2.approx.
// Error budget: attention term is ~25x diluted by the +qp residual.
// ---------------------------------------------------------------------------
#define ATQ 64
__global__ __launch_bounds__(128, 6) void attn_kernel() {
    const int b = blockIdx.y;
    const int h = blockIdx.z;
    const int s0 = g_starts[b];
    const int L  = g_starts[b + 1] - s0;
    const int q0 = blockIdx.x * ATQ;
    if (q0 >= L) return;

    // [key 0..31][d 0..31 bf16 + 8 pad] ; row stride 80B (conflict-free: 20r+m4)
    __shared__ __align__(16) uint16_t Ks[2][32][40];
    __shared__ __align__(16) uint16_t Vs[2][32][40];

    const int tid  = threadIdx.x;
    const int w    = tid >> 5;
    const int lane = tid & 31;
    const int g    = lane >> 2;
    const int m4   = lane & 3;

    const int q0w = q0 + w * 16;
    // 1/sqrt(32) * log2(e): softmax in log2 domain
    const float qs = 0.17677669529663687f * 1.4426950408889634f;

    const uint32_t ksb = (uint32_t)__cvta_generic_to_shared(&Ks[0][0][0]);
    const uint32_t vsb = (uint32_t)__cvta_generic_to_shared(&Vs[0][0][0]);

    auto issue_kv = [&](int ci, int buf) {
        int row   = tid >> 2;             // key 0..31
        int off16 = (tid & 3) * 16;       // 4 x 16B segments per 64B row
        int kg    = ci * 32 + row;
        int ok    = (kg < L) ? 16 : 0;
        int kr    = (kg < L) ? kg : 0;
        const char* gk = (const char*)&g_kp16[(s0 + kr) * 256 + h * 32] + off16;
        const char* gv = (const char*)&g_vp16[(s0 + kr) * 256 + h * 32] + off16;
        cp_async16(ksb + buf * 2560 + row * 80 + off16, gk, ok);
        cp_async16(vsb + buf * 2560 + row * 80 + off16, gv, ok);
    };

    // Q fragments: bf16x2 pairs, pre-scaled (qs), register-resident.
    uint32_t qa[2][4];
#pragma unroll
    for (int ks = 0; ks < 2; ks++) {
        int d0 = ks * 16 + 2 * m4;
        int r0 = q0w + g, r1 = q0w + g + 8;
        float2 z = make_float2(0.f, 0.f);
        float2 v00 = (r0 < L) ? *(const float2*)&g_qp[(s0 + r0) * 256 + h * 32 + d0]     : z;
        float2 v10 = (r1 < L) ? *(const float2*)&g_qp[(s0 + r1) * 256 + h * 32 + d0]     : z;
        float2 v01 = (r0 < L) ? *(const float2*)&g_qp[(s0 + r0) * 256 + h * 32 + d0 + 8] : z;
        float2 v11 = (r1 < L) ? *(const float2*)&g_qp[(s0 + r1) * 256 + h * 32 + d0 + 8] : z;
        qa[ks][0] = bf16pk(v00.x * qs, v00.y * qs);
        qa[ks][1] = bf16pk(v10.x * qs, v10.y * qs);
        qa[ks][2] = bf16pk(v01.x * qs, v01.y * qs);
        qa[ks][3] = bf16pk(v11.x * qs, v11.y * qs);
    }

    float o[4][4];
#pragma unroll
    for (int i = 0; i < 4; i++)
#pragma unroll
        for (int j = 0; j < 4; j++) o[i][j] = 0.f;
    float m0 = -1e30f, m1 = -1e30f, l0 = 0.f, l1 = 0.f;

    const int nc = (L + 31) >> 5;

    issue_kv(0, 0);
    cp_commit();

#pragma unroll 1
    for (int ci = 0; ci < nc; ci++) {
        const int buf = ci & 1;
        const int kc  = ci * 32;
        if (ci + 1 < nc) {
            issue_kv(ci + 1, buf ^ 1);
            cp_commit();
            asm volatile("cp.async.wait_group 1;" ::: "memory");
        } else {
            asm volatile("cp.async.wait_group 0;" ::: "memory");
        }
        __syncthreads();

        // ---- K fragments: 4x ldmatrix.x4 (non-trans) ----
        // call (ks,np): j0=b0[nt=2np], j1=b1[nt=2np], j2=b0[nt=2np+1], j3=b1[nt=2np+1]
        uint32_t kb[2][2][4];
        {
            int j = lane >> 3, r = lane & 7;
#pragma unroll
            for (int ks = 0; ks < 2; ks++)
#pragma unroll
                for (int np = 0; np < 2; np++) {
                    int key = np * 16 + ((j >> 1) << 3) + r;
                    int d   = ks * 16 + ((j & 1) << 3);
                    ldsm_x4(kb[ks][np], ksb + buf * 2560 + key * 80 + d * 2);
                }
        }

        // ---- QK^T: S[16][32] per warp (8 mma) ----
        float sc[4][4];
#pragma unroll
        for (int nt = 0; nt < 4; nt++)
#pragma unroll
            for (int j = 0; j < 4; j++) sc[nt][j] = 0.f;
#pragma unroll
        for (int ks = 0; ks < 2; ks++)
#pragma unroll
            for (int nt = 0; nt < 4; nt++)
                mma_bf16(sc[nt], qa[ks],
                         kb[ks][nt >> 1][(nt & 1) * 2],
                         kb[ks][nt >> 1][(nt & 1) * 2 + 1]);

        // ---- mask + online softmax (log2 domain) ----
        float mx0 = -1e30f, mx1 = -1e30f;
#pragma unroll
        for (int nt = 0; nt < 4; nt++) {
            int kcol0 = kc + nt * 8 + 2 * m4;
            if (kcol0 >= L)     { sc[nt][0] = -1e30f; sc[nt][2] = -1e30f; }
            if (kcol0 + 1 >= L) { sc[nt][1] = -1e30f; sc[nt][3] = -1e30f; }
            mx0 = fmaxf(mx0, fmaxf(sc[nt][0], sc[nt][1]));
            mx1 = fmaxf(mx1, fmaxf(sc[nt][2], sc[nt][3]));
        }
        mx0 = fmaxf(mx0, __shfl_xor_sync(0xffffffffu, mx0, 1));
        mx0 = fmaxf(mx0, __shfl_xor_sync(0xffffffffu, mx0, 2));
        mx1 = fmaxf(mx1, __shfl_xor_sync(0xffffffffu, mx1, 1));
        mx1 = fmaxf(mx1, __shfl_xor_sync(0xffffffffu, mx1, 2));

        float m0n = fmaxf(m0, mx0);
        float m1n = fmaxf(m1, mx1);
        float c0 = ex2(m0 - m0n);
        float c1 = ex2(m1 - m1n);
        m0 = m0n; m1 = m1n;

        float s0r = 0.f, s1r = 0.f;
#pragma unroll
        for (int nt = 0; nt < 4; nt++) {
            sc[nt][0] = ex2(sc[nt][0] - m0n);
            sc[nt][1] = ex2(sc[nt][1] - m0n);
            sc[nt][2] = ex2(sc[nt][2] - m1n);
            sc[nt][3] = ex2(sc[nt][3] - m1n);
            s0r += sc[nt][0] + sc[nt][1];
            s1r += sc[nt][2] + sc[nt][3];
        }
        s0r += __shfl_xor_sync(0xffffffffu, s0r, 1);
        s0r += __shfl_xor_sync(0xffffffffu, s0r, 2);
        s1r += __shfl_xor_sync(0xffffffffu, s1r, 1);
        s1r += __shfl_xor_sync(0xffffffffu, s1r, 2);
        l0 = l0 * c0 + s0r;
        l1 = l1 * c1 + s1r;

#pragma unroll
        for (int nt = 0; nt < 4; nt++) {
            o[nt][0] *= c0; o[nt][1] *= c0;
            o[nt][2] *= c1; o[nt][3] *= c1;
        }

        // ---- P pack: QK C-fragment IS the PV A-fragment (k16 identity) ----
        uint32_t pa[2][4];
#pragma unroll
        for (int ks = 0; ks < 2; ks++) {
            pa[ks][0] = bf16pk(sc[2 * ks][0],     sc[2 * ks][1]);
            pa[ks][1] = bf16pk(sc[2 * ks][2],     sc[2 * ks][3]);
            pa[ks][2] = bf16pk(sc[2 * ks + 1][0], sc[2 * ks + 1][1]);
            pa[ks][3] = bf16pk(sc[2 * ks + 1][2], sc[2 * ks + 1][3]);
        }

        // ---- V fragments: 4x ldmatrix.x4.trans ----
        // call (ks,dp): j0=b0[nt=2dp], j1=b1[nt=2dp], j2=b0[nt=2dp+1], j3=b1[nt=2dp+1]
        uint32_t vb[2][2][4];
        {
            int j = lane >> 3, r = lane & 7;
#pragma unroll
            for (int ks = 0; ks < 2; ks++)
#pragma unroll
                for (int dp = 0; dp < 2; dp++) {
                    int key = ks * 16 + ((j & 1) << 3) + r;
                    int d   = dp * 16 + ((j >> 1) << 3);
                    ldsm_x4_t(vb[ks][dp], vsb + buf * 2560 + key * 80 + d * 2);
                }
        }

        // ---- PV: O[16][32] += P @ V (8 mma) ----
#pragma unroll
        for (int ks = 0; ks < 2; ks++)
#pragma unroll
            for (int nt = 0; nt < 4; nt++)
                mma_bf16(o[nt], pa[ks],
                         vb[ks][nt >> 1][(nt & 1) * 2],
                         vb[ks][nt >> 1][(nt & 1) * 2 + 1]);

        __syncthreads();   // protect buf before next iteration's issue
    }

    // ---- epilogue: normalize, residual +qp, store ----
    float il0 = 1.f / l0, il1 = 1.f / l1;
    int r0 = q0w + g, r1 = q0w + g + 8;
#pragma unroll
    for (int nt = 0; nt < 4; nt++) {
        int dh = nt * 8 + 2 * m4;
        if (r0 < L) {
            int base = (s0 + r0) * 256 + h * 32 + dh;
            float2 qv = *(const float2*)&g_qp[base];
            *(float2*)&g_att[base] =
                make_float2(o[nt][0] * il0 + qv.x, o[nt][1] * il0 + qv.y);
        }
        if (r1 < L) {
            int base = (s0 + r1) * 256 + h * 32 + dh;
            float2 qv = *(const float2*)&g_qp[base];
            *(float2*)&g_att[base] =
                make_float2(o[nt][2] * il1 + qv.x, o[nt][3] * il1 + qv.y);
        }
    }
}

// ---------------------------------------------------------------------------
// Launch
// ---------------------------------------------------------------------------
extern "C" void kernel_launch(void* const* d_in, const int* in_sizes, int n_in,
                              void* d_out, int out_size) {
    const float* q   = (const float*)d_in[0];
    const float* k   = (const float*)d_in[1];
    const int* batch_q = (const int*)d_in[2];
    const float* Wq = (const float*)d_in[4];
    const float* bq = (const float*)d_in[5];
    const float* Wk = (const float*)d_in[6];
    const float* bk = (const float*)d_in[7];
    const float* Wv = (const float*)d_in[8];
    const float* bv = (const float*)d_in[9];
    const float* Wo = (const float*)d_in[10];
    const float* bo = (const float*)d_in[11];
    float* out = (float*)d_out;

    const int N = in_sizes[0] / 256;

    float* att; cudaGetSymbolAddress((void**)&att, g_att);

    starts_kernel<<<(N + 255) / 256, 256>>>(batch_q, N);

    dim3 pgrid((N + 63) / 64, 12);
    proj_kernel<<<pgrid, 128>>>(q, k, Wq, bq, Wk, bk, Wv, bv, N);

    dim3 agrid(1024 / ATQ, NB, 8);
    attn_kernel<<<agrid, 128>>>();

    dim3 ogrid((N + 63) / 64, 4);
    outgemm_kernel<<<ogrid, 128>>>(att, Wo, bo, out, N);
}